// round 1
// baseline (speedup 1.0000x reference)
#include <cuda_runtime.h>

// FurthestPoint sampling, B=16, N=65536, npoint=2048.
// Persistent multi-block design: 8 blocks per batch, all point state in registers,
// per-batch spin barrier through L2 (release/acquire) with double-buffered partials.

#define BATCHES 16
#define NPTS    65536
#define NPOINT  2048
#define NBLK    8          // blocks per batch (8*1024*8 = 65536 points)
#define THREADS 1024
#define PTS     8          // points per thread

__device__ float    g_pval[BATCHES][2][NBLK];
__device__ int      g_pidx[BATCHES][2][NBLK];
__device__ unsigned g_arrive[BATCHES];

__global__ void fps_init() {
    if (threadIdx.x < BATCHES) g_arrive[threadIdx.x] = 0u;
}

__device__ __forceinline__ unsigned ld_acquire(const unsigned* p) {
    unsigned v;
    asm volatile("ld.acquire.gpu.global.u32 %0, [%1];" : "=r"(v) : "l"(p) : "memory");
    return v;
}
__device__ __forceinline__ void red_release_add(unsigned* p, unsigned v) {
    asm volatile("red.release.gpu.global.add.u32 [%0], %1;" :: "l"(p), "r"(v) : "memory");
}

__global__ void __launch_bounds__(THREADS, 1)
fps_kernel(const float* __restrict__ xyz, float* __restrict__ out)
{
    const int b    = blockIdx.x / NBLK;
    const int blk  = blockIdx.x - b * NBLK;
    const int t    = threadIdx.x;
    const int lane = t & 31;
    const int wid  = t >> 5;

    const float* __restrict__ base = xyz + (size_t)b * NPTS * 3;
    float* __restrict__ out_idx = out;                                  // (B, NPOINT) idx as float
    float* __restrict__ out_smp = out + (size_t)BATCHES * NPOINT;       // (B, 3, NPOINT)

    __shared__ float s_rv[THREADS / 32];
    __shared__ int   s_ri[THREADS / 32];
    __shared__ float s_p[3];

    // Load this thread's 8 points into registers. One-time cost.
    const int pbase = (blk * THREADS + t) * PTS;
    float x[PTS], y[PTS], z[PTS], s[PTS];
#pragma unroll
    for (int k = 0; k < PTS; k++) {
        const float* q = base + (size_t)(pbase + k) * 3;
        x[k] = q[0]; y[k] = q[1]; z[k] = q[2];
        s[k] = 1e10f;   // matches reference BIG init
    }

    // First picked point is always index 0.
    float px = base[0], py = base[1], pz = base[2];
    if (blk == 0 && t == 0) {
        out_idx[(size_t)b * NPOINT] = 0.0f;
        out_smp[((size_t)b * 3 + 0) * NPOINT] = px;
        out_smp[((size_t)b * 3 + 1) * NPOINT] = py;
        out_smp[((size_t)b * 3 + 2) * NPOINT] = pz;
    }

    unsigned* arr = &g_arrive[b];

    for (int j = 1; j < NPOINT; j++) {
        // ---- distance update + per-thread argmax (all in registers) ----
        float bv = -1.0f;
        int   bi = 0x7fffffff;
#pragma unroll
        for (int k = 0; k < PTS; k++) {
            float dx = x[k] - px, dy = y[k] - py, dz = z[k] - pz;
            float d  = __fmaf_rn(dz, dz, __fmaf_rn(dy, dy, __fmul_rn(dx, dx)));
            float sn = fminf(s[k], d);
            s[k] = sn;
            if (sn > bv) { bv = sn; bi = pbase + k; }   // ties keep lowest index (k ascending)
        }

        // ---- warp argmax reduce (first-index tie break) ----
#pragma unroll
        for (int o = 16; o > 0; o >>= 1) {
            float ov = __shfl_down_sync(0xffffffffu, bv, o);
            int   oi = __shfl_down_sync(0xffffffffu, bi, o);
            if (ov > bv || (ov == bv && oi < bi)) { bv = ov; bi = oi; }
        }
        if (lane == 0) { s_rv[wid] = bv; s_ri[wid] = bi; }
        __syncthreads();

        // ---- block argmax reduce in warp 0 ----
        if (t < 32) {
            bv = s_rv[t]; bi = s_ri[t];
#pragma unroll
            for (int o = 16; o > 0; o >>= 1) {
                float ov = __shfl_down_sync(0xffffffffu, bv, o);
                int   oi = __shfl_down_sync(0xffffffffu, bi, o);
                if (ov > bv || (ov == bv && oi < bi)) { bv = ov; bi = oi; }
            }
            if (t == 0) {
                const int buf = j & 1;   // double-buffered partial slots
                __stcg(&g_pval[b][buf][blk], bv);
                __stcg(&g_pidx[b][buf][blk], bi);
                red_release_add(arr, 1u);

                const unsigned target = (unsigned)j * NBLK;
                while (ld_acquire(arr) < target) __nanosleep(64);

                // all 8 blocks redundantly reduce the 8 partials -> identical winner
                float wv = __ldcg(&g_pval[b][buf][0]);
                int   wi = __ldcg(&g_pidx[b][buf][0]);
#pragma unroll
                for (int i = 1; i < NBLK; i++) {
                    float v  = __ldcg(&g_pval[b][buf][i]);
                    int   ix = __ldcg(&g_pidx[b][buf][i]);
                    if (v > wv || (v == wv && ix < wi)) { wv = v; wi = ix; }
                }
                const float* q = base + (size_t)wi * 3;   // L2-resident
                float qx = q[0], qy = q[1], qz = q[2];
                s_p[0] = qx; s_p[1] = qy; s_p[2] = qz;
                if (blk == 0) {
                    out_idx[(size_t)b * NPOINT + j] = (float)wi;
                    out_smp[((size_t)b * 3 + 0) * NPOINT + j] = qx;
                    out_smp[((size_t)b * 3 + 1) * NPOINT + j] = qy;
                    out_smp[((size_t)b * 3 + 2) * NPOINT + j] = qz;
                }
            }
        }
        __syncthreads();
        px = s_p[0]; py = s_p[1]; pz = s_p[2];
    }
}

extern "C" void kernel_launch(void* const* d_in, const int* in_sizes, int n_in,
                              void* d_out, int out_size) {
    (void)in_sizes; (void)n_in; (void)out_size;
    const float* xyz = (const float*)d_in[0];
    float* out = (float*)d_out;
    fps_init<<<1, 32>>>();
    fps_kernel<<<BATCHES * NBLK, THREADS>>>(xyz, out);
}